// round 6
// baseline (speedup 1.0000x reference)
#include <cuda_runtime.h>
#include <cuda_fp16.h>
#include <cstdint>

// Problem dims
#define LDIM 128
#define BDIM 2048
#define DDIM 300
#define HDIM 60
#define HPAD 64
#define MDIM (LDIM * BDIM)  // 262144

// GEMM tiling
#define KC   32            // K per chunk
#define NCH  10            // ceil(300/32), K padded to 320
#define MT   256           // M rows per block
#define SAS  36            // sA row stride (floats): conflict-free fragment reads
#define NBUF 3             // cp.async pipeline depth

// Scratch (static device globals — no allocation)
__device__ __half  g_q[(size_t)MDIM * HPAD];    // projected (fp16), padded to 64 cols
__device__ float2  g_w[MDIM];                   // (w0, w2); w1 = 1 - w0 - w2
__device__ float2  g_bpack[NCH * 1024];         // pre-packed B fragments per chunk

__device__ __forceinline__ uint32_t smem_u32(const void* p) {
    uint32_t a;
    asm("{ .reg .u64 t; cvta.to.shared.u64 t, %1; cvt.u32.u64 %0, t; }" : "=r"(a) : "l"(p));
    return a;
}
__device__ __forceinline__ uint32_t f2tf32(float x) {
    uint32_t u;
    asm("cvt.rna.tf32.f32 %0, %1;" : "=r"(u) : "f"(x));
    return u;
}
__device__ __forceinline__ void mma_tf32(float* c, uint32_t a0, uint32_t a1,
                                         uint32_t a2, uint32_t a3,
                                         uint32_t b0, uint32_t b1) {
    asm volatile(
        "mma.sync.aligned.m16n8k8.row.col.f32.tf32.tf32.f32 "
        "{%0,%1,%2,%3}, {%4,%5,%6,%7}, {%8,%9}, {%0,%1,%2,%3};"
        : "+f"(c[0]), "+f"(c[1]), "+f"(c[2]), "+f"(c[3])
        : "r"(a0), "r"(a1), "r"(a2), "r"(a3), "r"(b0), "r"(b1));
}
__device__ __forceinline__ void cp16(uint32_t dst, const void* src, int sz) {
    asm volatile("cp.async.cg.shared.global [%0], [%1], 16, %2;"
                 :: "r"(dst), "l"(src), "r"(sz));
}
#define CP_COMMIT() asm volatile("cp.async.commit_group;" ::: "memory")
#define CP_WAIT0()  asm volatile("cp.async.wait_group 0;" ::: "memory")
#define CP_WAIT1()  asm volatile("cp.async.wait_group 1;" ::: "memory")

// ---------------------------------------------------------------------------
// Kernel 0 (one-shot, tiny): pack B fragments for all chunks.
// ---------------------------------------------------------------------------
__global__ void k_packB(const float* __restrict__ P) {
    const int e = blockIdx.x * 256 + threadIdx.x;   // < 10240
    if (e >= NCH * 1024) return;
    const int c  = e >> 10;
    const int r  = e & 1023;
    const int ks = r >> 8;
    const int n  = (r >> 5) & 7;
    const int ln = r & 31;
    const int tg = ln & 3, g = ln >> 2;
    const int k  = c * KC + 8 * ks + tg;
    const int h  = 8 * n + g;
    float b0 = (k < DDIM && h < HDIM)     ? P[(size_t)k * HDIM + h]       : 0.f;
    float b1 = (k + 4 < DDIM && h < HDIM) ? P[(size_t)(k + 4) * HDIM + h] : 0.f;
    float2 v;
    v.x = __uint_as_float(f2tf32(b0));
    v.y = __uint_as_float(f2tf32(b1));
    g_bpack[e] = v;
}

// ---------------------------------------------------------------------------
// Kernel 1: q = sentence @ proj via m16n8k8 tf32.
// 3-stage cp.async A pipeline (2 chunks always in flight); B fragments read
// straight from g_bpack via __ldg (80 KB, L1/L2-resident, coalesced).
// 256 threads / 8 warps; M=256 per block (2 m16 tiles/warp), N=64.
// ---------------------------------------------------------------------------
__global__ __launch_bounds__(256, 2) void k_gemm_mma(const float* __restrict__ A,
                                                     const float* __restrict__ P) {
    extern __shared__ float sm[];                  // [NBUF][MT][SAS]
    const uint32_t* sAu = reinterpret_cast<const uint32_t*>(sm);

    const int tid  = threadIdx.x;
    const int w    = tid >> 5;
    const int lane = tid & 31;
    const int g    = lane >> 2;
    const int tig  = lane & 3;
    const int bm   = blockIdx.x * MT;

    const float*   arow = A + (size_t)(bm + tid) * DDIM;
    const uint32_t sA_u = smem_u32(sm);

    float acc0[8][4], acc1[8][4];
#pragma unroll
    for (int n = 0; n < 8; ++n)
#pragma unroll
        for (int i = 0; i < 4; ++i) { acc0[n][i] = 0.f; acc1[n][i] = 0.f; }

    auto stageA = [&](int c, int buf) {
#pragma unroll
        for (int i = 0; i < 8; ++i) {
            const int k  = c * KC + 4 * i;
            const int sz = (k + 4 <= DDIM) ? 16 : 0;
            const float* src = sz ? (arow + k) : A;
            const uint32_t dst = sA_u + (((buf * MT + tid) * SAS + 4 * i) << 2);
            cp16(dst, src, sz);
        }
        CP_COMMIT();
    };

    stageA(0, 0);
    stageA(1, 1);

    const int rbase = 32 * w + g;

    for (int c = 0; c < NCH; ++c) {
        const int buf = c % NBUF;
        if (c + 2 < NCH) CP_WAIT1();   // A(c) landed; A(c+1) may be in flight
        else             CP_WAIT0();
        __syncthreads();               // all warps done with mma(c-1)

        if (c + 2 < NCH)
            stageA(c + 2, (c + 2) % NBUF);

        const float2* bp = g_bpack + c * 1024 + lane;
#pragma unroll
        for (int ks = 0; ks < 4; ++ks) {
            const int kk = 8 * ks;
            const int r0 = (buf * MT + rbase) * SAS + kk + tig;
            const uint32_t a00 = sAu[r0];
            const uint32_t a01 = sAu[r0 + 8 * SAS];
            const uint32_t a02 = sAu[r0 + 4];
            const uint32_t a03 = sAu[r0 + 8 * SAS + 4];
            const uint32_t a10 = sAu[r0 + 16 * SAS];
            const uint32_t a11 = sAu[r0 + 24 * SAS];
            const uint32_t a12 = sAu[r0 + 16 * SAS + 4];
            const uint32_t a13 = sAu[r0 + 24 * SAS + 4];
#pragma unroll
            for (int n = 0; n < 8; ++n) {
                const float2 b = __ldg(bp + (ks * 8 + n) * 32);
                const uint32_t b0 = __float_as_uint(b.x);
                const uint32_t b1 = __float_as_uint(b.y);
                mma_tf32(acc0[n], a00, a01, a02, a03, b0, b1);
                mma_tf32(acc1[n], a10, a11, a12, a13, b0, b1);
            }
        }
    }

    // ---- epilogue: fp16 q; thread writes half2 (cols 2tig,2tig+1) per n, 4 rows
    __half* d00 = g_q + ((size_t)bm + rbase) * HPAD;
    __half* d01 = g_q + ((size_t)bm + rbase + 8) * HPAD;
    __half* d10 = g_q + ((size_t)bm + rbase + 16) * HPAD;
    __half* d11 = g_q + ((size_t)bm + rbase + 24) * HPAD;
#pragma unroll
    for (int n = 0; n < 8; ++n) {
        const int col = 8 * n + 2 * tig;
        *reinterpret_cast<__half2*>(d00 + col) = __floats2half2_rn(acc0[n][0], acc0[n][1]);
        *reinterpret_cast<__half2*>(d01 + col) = __floats2half2_rn(acc0[n][2], acc0[n][3]);
        *reinterpret_cast<__half2*>(d10 + col) = __floats2half2_rn(acc1[n][0], acc1[n][1]);
        *reinterpret_cast<__half2*>(d11 + col) = __floats2half2_rn(acc1[n][2], acc1[n][3]);
    }
}

// ---------------------------------------------------------------------------
// Kernel 2: per-b column — row norms, neighbor dots, masked 3-way softmax.
// ---------------------------------------------------------------------------
__global__ __launch_bounds__(128) void k_simw(const int* __restrict__ size) {
    const int b    = blockIdx.x;
    const int tid  = threadIdx.x;
    const int w    = tid >> 5;
    const int lane = tid & 31;

    __shared__ float nrm[LDIM];
    __shared__ float crs[LDIM];

    const int r0 = w * 32;
    float2 p = make_float2(0.f, 0.f);
    if (w > 0) {
        const __half2* row = reinterpret_cast<const __half2*>(
            g_q + ((size_t)(r0 - 1) * BDIM + b) * HPAD);
        p = __half22float2(row[lane]);
    }
    for (int r = r0; r < r0 + 32; ++r) {
        const __half2* row = reinterpret_cast<const __half2*>(
            g_q + ((size_t)r * BDIM + b) * HPAD);
        float2 v = __half22float2(row[lane]);
        float nn = v.x * v.x + v.y * v.y;
        float cc = v.x * p.x + v.y * p.y;
#pragma unroll
        for (int off = 16; off; off >>= 1) {
            nn += __shfl_xor_sync(0xffffffffu, nn, off);
            cc += __shfl_xor_sync(0xffffffffu, cc, off);
        }
        if (lane == 0) {
            nrm[r] = fmaxf(nn, 1e-5f);
            if (r > 0) crs[r - 1] = cc;
        }
        p = v;
    }
    __syncthreads();

    const int l  = tid;
    const int sz = size[b];
    float a0 = -1e30f, a2 = -1e30f;
    if (l >= 1 && l < sz)
        a0 = crs[l - 1] / (nrm[l - 1] * nrm[l]);
    int lim2 = sz - 1; if (lim2 < 0) lim2 = 0;
    if (l < lim2)
        a2 = crs[l] / (nrm[l] * nrm[l + 1]);

    float mx = fmaxf(1.0f, fmaxf(a0, a2));
    float e0 = expf(a0 - mx);
    float e1 = expf(1.0f - mx);
    float e2 = expf(a2 - mx);
    float inv = 1.0f / (e0 + e1 + e2);
    g_w[l * BDIM + b] = make_float2(e0 * inv, e2 * inv);
}

// ---------------------------------------------------------------------------
// Kernel 3: out[l,b,:] = w1*s[l] + w0*s[l-1] + w2*s[l+1].
// Thread owns one (b, j) column over a 32-long l-segment, register rotation.
// 4 segments -> grid 2400 (vs 600): 4x concurrency, +2.3% boundary re-reads.
// Boundary weights are exactly zero where prev/nxt are out of range.
// ---------------------------------------------------------------------------
#define LSTRIDE ((size_t)BDIM * 75)   // float4 stride between l-planes
#define SEG 32

__global__ __launch_bounds__(256) void k_combine(const float* __restrict__ S,
                                                 float* __restrict__ out) {
    const int t   = blockIdx.x * 256 + threadIdx.x;  // < 614400
    const int seg = t / (BDIM * 75);
    const int rem = t - seg * (BDIM * 75);
    const int b   = rem / 75;
    const int j   = rem - b * 75;
    const int l0  = seg * SEG;

    const float4* sp = reinterpret_cast<const float4*>(S) + (size_t)b * 75 + j;
    float4*       op = reinterpret_cast<float4*>(out) + (size_t)b * 75 + j;
    const float2* wp = g_w + b;

    float4 prev = (l0 > 0) ? __ldcs(sp + (size_t)(l0 - 1) * LSTRIDE)
                           : make_float4(0.f, 0.f, 0.f, 0.f);
    float4 cur  = __ldcs(sp + (size_t)l0 * LSTRIDE);
    float4 nxt;

#pragma unroll 8
    for (int i = 0; i < SEG; ++i) {
        const int l = l0 + i;
        if (l < LDIM - 1) nxt = __ldcs(sp + (size_t)(l + 1) * LSTRIDE);
        else              nxt = make_float4(0.f, 0.f, 0.f, 0.f);

        const float2 ww = __ldg(wp + (size_t)l * BDIM);
        const float w0 = ww.x, w2 = ww.y, w1 = 1.0f - w0 - w2;

        float4 r;
        r.x = w1 * cur.x; r.y = w1 * cur.y; r.z = w1 * cur.z; r.w = w1 * cur.w;
        r.x = fmaf(w0, prev.x, r.x); r.y = fmaf(w0, prev.y, r.y);
        r.z = fmaf(w0, prev.z, r.z); r.w = fmaf(w0, prev.w, r.w);
        r.x = fmaf(w2, nxt.x, r.x);  r.y = fmaf(w2, nxt.y, r.y);
        r.z = fmaf(w2, nxt.z, r.z);  r.w = fmaf(w2, nxt.w, r.w);

        __stcs(op + (size_t)l * LSTRIDE, r);
        prev = cur;
        cur  = nxt;
    }
}

// ---------------------------------------------------------------------------
extern "C" void kernel_launch(void* const* d_in, const int* in_sizes, int n_in,
                              void* d_out, int out_size) {
    const float* sentence = nullptr;
    const int*   size_arr = nullptr;
    const float* proj     = nullptr;
    for (int i = 0; i < n_in; ++i) {
        if (in_sizes[i] == LDIM * BDIM * DDIM)      sentence = (const float*)d_in[i];
        else if (in_sizes[i] == DDIM * HDIM)        proj     = (const float*)d_in[i];
        else if (in_sizes[i] == BDIM)               size_arr = (const int*)d_in[i];
    }
    float* out = (float*)d_out;

    const int smem_bytes = NBUF * MT * SAS * 4;   // 110592
    cudaFuncSetAttribute(k_gemm_mma, cudaFuncAttributeMaxDynamicSharedMemorySize,
                         smem_bytes);

    k_packB<<<(NCH * 1024 + 255) / 256, 256>>>(proj);
    k_gemm_mma<<<MDIM / MT, 256, smem_bytes>>>(sentence, proj);
    k_simw<<<BDIM, 128>>>(size_arr);
    k_combine<<<(BDIM * 75 * (LDIM / SEG)) / 256, 256>>>(sentence, out);
}

// round 7
// speedup vs baseline: 1.0389x; 1.0389x over previous
#include <cuda_runtime.h>
#include <cstdint>

// Problem dims
#define LDIM 128
#define BDIM 2048
#define DDIM 300
#define HDIM 60
#define HPAD 64
#define MDIM (LDIM * BDIM)

// GEMM tiling (per block: M=128 l-rows at fixed b, N=64, K=300->320)
#define KC   32
#define NCH  10
#define SAS  36            // A smem row stride (floats)
#define NBUF 3             // cp.async pipeline depth (2 chunks in flight)
#define QST  66            // q smem row stride (floats), pad kills write conflicts

// Pre-packed B fragments (tf32 bits), 80 KB, L2-resident
__device__ float2 g_bpack[NCH * 1024];

__device__ __forceinline__ uint32_t smem_u32(const void* p) {
    uint32_t a;
    asm("{ .reg .u64 t; cvta.to.shared.u64 t, %1; cvt.u32.u64 %0, t; }" : "=r"(a) : "l"(p));
    return a;
}
__device__ __forceinline__ uint32_t f2tf32(float x) {
    uint32_t u;
    asm("cvt.rna.tf32.f32 %0, %1;" : "=r"(u) : "f"(x));
    return u;
}
__device__ __forceinline__ void mma_tf32(float* c, uint32_t a0, uint32_t a1,
                                         uint32_t a2, uint32_t a3,
                                         uint32_t b0, uint32_t b1) {
    asm volatile(
        "mma.sync.aligned.m16n8k8.row.col.f32.tf32.tf32.f32 "
        "{%0,%1,%2,%3}, {%4,%5,%6,%7}, {%8,%9}, {%0,%1,%2,%3};"
        : "+f"(c[0]), "+f"(c[1]), "+f"(c[2]), "+f"(c[3])
        : "r"(a0), "r"(a1), "r"(a2), "r"(a3), "r"(b0), "r"(b1));
}
__device__ __forceinline__ void cp16(uint32_t dst, const void* src, int sz) {
    asm volatile("cp.async.cg.shared.global [%0], [%1], 16, %2;"
                 :: "r"(dst), "l"(src), "r"(sz));
}
#define CP_COMMIT() asm volatile("cp.async.commit_group;" ::: "memory")
#define CP_WAIT0()  asm volatile("cp.async.wait_group 0;" ::: "memory")
#define CP_WAIT1()  asm volatile("cp.async.wait_group 1;" ::: "memory")

// ---------------------------------------------------------------------------
// Kernel 0 (one-shot, tiny): pack B fragments for all chunks.
// ---------------------------------------------------------------------------
__global__ void k_packB(const float* __restrict__ P) {
    const int e = blockIdx.x * 256 + threadIdx.x;   // < 10240
    if (e >= NCH * 1024) return;
    const int c  = e >> 10;
    const int r  = e & 1023;
    const int ks = r >> 8;
    const int n  = (r >> 5) & 7;
    const int ln = r & 31;
    const int tg = ln & 3, g = ln >> 2;
    const int k  = c * KC + 8 * ks + tg;
    const int h  = 8 * n + g;
    float b0 = (k < DDIM && h < HDIM)     ? P[(size_t)k * HDIM + h]       : 0.f;
    float b1 = (k + 4 < DDIM && h < HDIM) ? P[(size_t)(k + 4) * HDIM + h] : 0.f;
    float2 v;
    v.x = __uint_as_float(f2tf32(b0));
    v.y = __uint_as_float(f2tf32(b1));
    g_bpack[e] = v;
}

// ---------------------------------------------------------------------------
// Fused kernel: one block per b. Phases:
//  1) pipelined tf32 MMA: q[128 x 64] = S[:, b, :] @ P   (q stays in smem)
//  2) norms + neighbor dots + masked softmax -> w[128] in smem
//  3) combine: out[l,b,:] = w1*s[l] + w0*s[l-1] + w2*s[l+1]  (s rows L2-hot)
// Smem: A 3*128*36*4 = 55296 | q 128*66*4 = 33792 | nrm/crs 1024 | w 1024
// ---------------------------------------------------------------------------
__global__ __launch_bounds__(256, 2) void k_fused(const float* __restrict__ S,
                                                  const int* __restrict__ size,
                                                  float* __restrict__ out) {
    extern __shared__ float sm[];
    float* sA   = sm;                         // [NBUF][128][SAS]
    float* q_sm = sm + NBUF * LDIM * SAS;     // [128][QST]
    float* nrm  = q_sm + LDIM * QST;          // [128]
    float* crs  = nrm + LDIM;                 // [128]
    float2* wsm = reinterpret_cast<float2*>(crs + LDIM);  // [128]
    const uint32_t* sAu = reinterpret_cast<const uint32_t*>(sA);

    const int tid  = threadIdx.x;
    const int w    = tid >> 5;
    const int lane = tid & 31;
    const int g    = lane >> 2;
    const int tig  = lane & 3;
    const int b    = blockIdx.x;

    // ======================= Phase 1: GEMM =======================
    const int srow  = tid >> 1;       // staging: 2 threads per l-row
    const int shalf = tid & 1;
    const float* sgp = S + ((size_t)srow * BDIM + b) * DDIM + shalf * 16;
    const uint32_t sA_u = smem_u32(sA);

    auto stageA = [&](int c, int buf) {
#pragma unroll
        for (int i = 0; i < 4; ++i) {
            const int k  = c * KC + shalf * 16 + 4 * i;
            const int sz = (k + 4 <= DDIM) ? 16 : 0;
            const float* src = sz ? (sgp + c * KC + 4 * i) : S;
            const uint32_t dst = sA_u + (((buf * LDIM + srow) * SAS + shalf * 16 + 4 * i) << 2);
            cp16(dst, src, sz);
        }
        CP_COMMIT();
    };

    float acc[8][4];
#pragma unroll
    for (int n = 0; n < 8; ++n)
#pragma unroll
        for (int i = 0; i < 4; ++i) acc[n][i] = 0.f;

    stageA(0, 0);
    stageA(1, 1);

    const int rbase = 16 * w + g;     // warp w owns l-rows 16w..16w+15

    for (int c = 0; c < NCH; ++c) {
        const int buf = c % NBUF;
        if (c + 2 < NCH) CP_WAIT1();
        else             CP_WAIT0();
        __syncthreads();

        if (c + 2 < NCH) stageA(c + 2, (c + 2) % NBUF);

        const float2* bp = g_bpack + c * 1024 + lane;
#pragma unroll
        for (int ks = 0; ks < 4; ++ks) {
            const int kk = 8 * ks;
            const int r0 = (buf * LDIM + rbase) * SAS + kk + tig;
            const uint32_t a0 = sAu[r0];
            const uint32_t a1 = sAu[r0 + 8 * SAS];
            const uint32_t a2 = sAu[r0 + 4];
            const uint32_t a3 = sAu[r0 + 8 * SAS + 4];
#pragma unroll
            for (int n = 0; n < 8; ++n) {
                const float2 bb = __ldg(bp + (ks * 8 + n) * 32);
                mma_tf32(acc[n], a0, a1, a2, a3,
                         __float_as_uint(bb.x), __float_as_uint(bb.y));
            }
        }
    }

    // q tile -> smem (fp32). c0,c1 -> row rbase; c2,c3 -> row rbase+8.
#pragma unroll
    for (int n = 0; n < 8; ++n) {
        const int col = 8 * n + 2 * tig;
        *reinterpret_cast<float2*>(q_sm + rbase * QST + col)       = make_float2(acc[n][0], acc[n][1]);
        *reinterpret_cast<float2*>(q_sm + (rbase + 8) * QST + col) = make_float2(acc[n][2], acc[n][3]);
    }
    __syncthreads();

    // ======================= Phase 2: weights =======================
    // Warp w scans l-rows 16w..16w+15; lane holds cols 2lane, 2lane+1.
    {
        const int r0 = 16 * w;
        float2 p = make_float2(0.f, 0.f);
        if (w > 0) p = *reinterpret_cast<const float2*>(q_sm + (r0 - 1) * QST + 2 * lane);
        for (int r = r0; r < r0 + 16; ++r) {
            float2 v = *reinterpret_cast<const float2*>(q_sm + r * QST + 2 * lane);
            float nn = v.x * v.x + v.y * v.y;
            float cc = v.x * p.x + v.y * p.y;
#pragma unroll
            for (int off = 16; off; off >>= 1) {
                nn += __shfl_xor_sync(0xffffffffu, nn, off);
                cc += __shfl_xor_sync(0xffffffffu, cc, off);
            }
            if (lane == 0) {
                nrm[r] = fmaxf(nn, 1e-5f);
                if (r > 0) crs[r - 1] = cc;
            }
            p = v;
        }
    }
    __syncthreads();

    if (tid < LDIM) {
        const int l  = tid;
        const int sz = size[b];
        float a0 = -1e30f, a2 = -1e30f;
        if (l >= 1 && l < sz)
            a0 = crs[l - 1] / (nrm[l - 1] * nrm[l]);
        int lim2 = sz - 1; if (lim2 < 0) lim2 = 0;
        if (l < lim2)
            a2 = crs[l] / (nrm[l] * nrm[l + 1]);

        float mx = fmaxf(1.0f, fmaxf(a0, a2));
        float e0 = expf(a0 - mx);
        float e1 = expf(1.0f - mx);
        float e2 = expf(a2 - mx);
        float inv = 1.0f / (e0 + e1 + e2);
        wsm[l] = make_float2(e0 * inv, e2 * inv);
    }
    __syncthreads();

    // ======================= Phase 3: combine =======================
    // 128 l-rows x 75 float4 each; neighbor rows are L2-hot (just streamed).
    const float4* s4 = reinterpret_cast<const float4*>(S);
    float4*       o4 = reinterpret_cast<float4*>(out);
    for (int idx = tid; idx < LDIM * 75; idx += 256) {
        const int l = idx / 75;
        const int j = idx - l * 75;
        const size_t base = ((size_t)l * BDIM + b) * 75 + j;

        const float2 ww = wsm[l];
        const float w0 = ww.x, w2 = ww.y, w1 = 1.0f - w0 - w2;

        float4 cu = __ldg(s4 + base);
        float4 r;
        r.x = w1 * cu.x; r.y = w1 * cu.y; r.z = w1 * cu.z; r.w = w1 * cu.w;
        if (l > 0) {
            float4 pv = __ldg(s4 + base - (size_t)BDIM * 75);
            r.x = fmaf(w0, pv.x, r.x); r.y = fmaf(w0, pv.y, r.y);
            r.z = fmaf(w0, pv.z, r.z); r.w = fmaf(w0, pv.w, r.w);
        }
        if (l < LDIM - 1) {
            float4 nx = __ldg(s4 + base + (size_t)BDIM * 75);
            r.x = fmaf(w2, nx.x, r.x); r.y = fmaf(w2, nx.y, r.y);
            r.z = fmaf(w2, nx.z, r.z); r.w = fmaf(w2, nx.w, r.w);
        }
        __stcs(o4 + base, r);
    }
}

// ---------------------------------------------------------------------------
extern "C" void kernel_launch(void* const* d_in, const int* in_sizes, int n_in,
                              void* d_out, int out_size) {
    const float* sentence = nullptr;
    const int*   size_arr = nullptr;
    const float* proj     = nullptr;
    for (int i = 0; i < n_in; ++i) {
        if (in_sizes[i] == LDIM * BDIM * DDIM)      sentence = (const float*)d_in[i];
        else if (in_sizes[i] == DDIM * HDIM)        proj     = (const float*)d_in[i];
        else if (in_sizes[i] == BDIM)               size_arr = (const int*)d_in[i];
    }
    float* out = (float*)d_out;

    const int smem_bytes = NBUF * LDIM * SAS * 4       // A pipeline  55296
                         + LDIM * QST * 4              // q tile      33792
                         + 2 * LDIM * 4                // nrm, crs     1024
                         + LDIM * 8;                   // weights      1024
    cudaFuncSetAttribute(k_fused, cudaFuncAttributeMaxDynamicSharedMemorySize,
                         smem_bytes);

    k_packB<<<(NCH * 1024 + 255) / 256, 256>>>(proj);
    k_fused<<<BDIM, 256, smem_bytes>>>(sentence, size_arr, out);
}

// round 8
// speedup vs baseline: 1.0569x; 1.0173x over previous
#include <cuda_runtime.h>
#include <cstdint>

// Problem dims
#define LDIM 128
#define BDIM 2048
#define DDIM 300
#define HDIM 60

// Fused-kernel layout
#define KC    32
#define NCH   10
#define SRS   308          // S smem row stride (floats); (g*20+tig)%32 all distinct
#define QST   66           // q smem row stride (floats)
#define NTHR  512

// Pre-packed B fragments (tf32 bits), 80 KB, L2-resident
__device__ float2 g_bpack[NCH * 1024];

__device__ __forceinline__ uint32_t smem_u32(const void* p) {
    uint32_t a;
    asm("{ .reg .u64 t; cvta.to.shared.u64 t, %1; cvt.u32.u64 %0, t; }" : "=r"(a) : "l"(p));
    return a;
}
__device__ __forceinline__ uint32_t f2tf32(float x) {
    uint32_t u;
    asm("cvt.rna.tf32.f32 %0, %1;" : "=r"(u) : "f"(x));
    return u;
}
__device__ __forceinline__ void mma_tf32(float* c, uint32_t a0, uint32_t a1,
                                         uint32_t a2, uint32_t a3,
                                         uint32_t b0, uint32_t b1) {
    asm volatile(
        "mma.sync.aligned.m16n8k8.row.col.f32.tf32.tf32.f32 "
        "{%0,%1,%2,%3}, {%4,%5,%6,%7}, {%8,%9}, {%0,%1,%2,%3};"
        : "+f"(c[0]), "+f"(c[1]), "+f"(c[2]), "+f"(c[3])
        : "r"(a0), "r"(a1), "r"(a2), "r"(a3), "r"(b0), "r"(b1));
}
__device__ __forceinline__ void cp16(uint32_t dst, const void* src, int sz) {
    asm volatile("cp.async.cg.shared.global [%0], [%1], 16, %2;"
                 :: "r"(dst), "l"(src), "r"(sz));
}
#define CP_COMMIT() asm volatile("cp.async.commit_group;" ::: "memory")

__device__ __forceinline__ void cp_wait_n(int n) {
    switch (n) {
        case 0: asm volatile("cp.async.wait_group 0;" ::: "memory"); break;
        case 1: asm volatile("cp.async.wait_group 1;" ::: "memory"); break;
        case 2: asm volatile("cp.async.wait_group 2;" ::: "memory"); break;
        case 3: asm volatile("cp.async.wait_group 3;" ::: "memory"); break;
        case 4: asm volatile("cp.async.wait_group 4;" ::: "memory"); break;
        case 5: asm volatile("cp.async.wait_group 5;" ::: "memory"); break;
        case 6: asm volatile("cp.async.wait_group 6;" ::: "memory"); break;
        case 7: asm volatile("cp.async.wait_group 7;" ::: "memory"); break;
        case 8: asm volatile("cp.async.wait_group 8;" ::: "memory"); break;
        default: asm volatile("cp.async.wait_group 9;" ::: "memory"); break;
    }
}

// ---------------------------------------------------------------------------
// Kernel 0 (one-shot, tiny): pack B fragments for all chunks (zero-padded
// past K=300 and H=60).
// ---------------------------------------------------------------------------
__global__ void k_packB(const float* __restrict__ P) {
    const int e = blockIdx.x * 256 + threadIdx.x;   // < 10240
    if (e >= NCH * 1024) return;
    const int c  = e >> 10;
    const int r  = e & 1023;
    const int ks = r >> 8;
    const int n  = (r >> 5) & 7;
    const int ln = r & 31;
    const int tg = ln & 3, g = ln >> 2;
    const int k  = c * KC + 8 * ks + tg;
    const int h  = 8 * n + g;
    float b0 = (k < DDIM && h < HDIM)     ? P[(size_t)k * HDIM + h]       : 0.f;
    float b1 = (k + 4 < DDIM && h < HDIM) ? P[(size_t)(k + 4) * HDIM + h] : 0.f;
    float2 v;
    v.x = __uint_as_float(f2tf32(b0));
    v.y = __uint_as_float(f2tf32(b1));
    g_bpack[e] = v;
}

// ---------------------------------------------------------------------------
// Fused kernel, one CTA per b. The ENTIRE S[:, b, :] column (128 x 300 fp32,
// padded to 308) lives in smem:
//  1) all cp.async chunks issued upfront; per-chunk wait + MMA (warps 0-7)
//  2) norms / neighbor-dots / masked softmax from q smem
//  3) combine reads prev/cur/next rows from SMEM, streams out to DRAM
// Smem: S 128*308*4=157696 | q 128*66*4=33792 | nrm+crs 1024 | w 1024 = 193536
// ---------------------------------------------------------------------------
__global__ __launch_bounds__(NTHR, 1) void k_fused(const float* __restrict__ S,
                                                   const int* __restrict__ size,
                                                   float* __restrict__ out) {
    extern __shared__ float sm[];
    float*  s_sm = sm;                        // [128][SRS]
    float*  q_sm = sm + LDIM * SRS;           // [128][QST]
    float*  nrm  = q_sm + LDIM * QST;         // [128]
    float*  crs  = nrm + LDIM;                // [128]
    float2* wsm  = reinterpret_cast<float2*>(crs + LDIM);  // [128]
    const uint32_t* sAu = reinterpret_cast<const uint32_t*>(s_sm);

    const int tid  = threadIdx.x;
    const int w    = tid >> 5;
    const int lane = tid & 31;
    const int g    = lane >> 2;
    const int tig  = lane & 3;
    const int b    = blockIdx.x;

    const uint32_t s_u = smem_u32(s_sm);

    // ---- issue ALL chunks: thread owns slots tid*2, tid*2+1 of each chunk ----
    // slot -> row = slot>>3, q8 = slot&7 ; k = c*32 + q8*4
#pragma unroll
    for (int c = 0; c < NCH; ++c) {
#pragma unroll
        for (int i = 0; i < 2; ++i) {
            const int slot = tid * 2 + i;
            const int row  = slot >> 3;
            const int k    = c * KC + (slot & 7) * 4;
            if (k < SRS) {                            // k >= 308 never stored
                const int sz = (k + 4 <= DDIM) ? 16 : 0;   // 300..307 -> zero-fill
                const float* src = sz ? S + ((size_t)row * BDIM + b) * DDIM + k : S;
                cp16(s_u + ((row * SRS + k) << 2), src, sz);
            }
        }
        CP_COMMIT();
    }

    // ---- MMA: warps 0-7 own 16 l-rows each ----
    float acc[8][4];
#pragma unroll
    for (int n = 0; n < 8; ++n)
#pragma unroll
        for (int i = 0; i < 4; ++i) acc[n][i] = 0.f;

    const int rbase = 16 * w + g;

#pragma unroll
    for (int c = 0; c < NCH; ++c) {
        cp_wait_n(NCH - 1 - c);
        __syncthreads();

        if (w < 8) {
            const float2* bp = g_bpack + c * 1024 + lane;
            const int nks = (c == NCH - 1) ? 2 : 4;   // chunk 9: k>=304 is all-zero B
#pragma unroll
            for (int ks = 0; ks < 4; ++ks) {
                if (ks >= nks) break;
                const int r0 = rbase * SRS + c * KC + 8 * ks + tig;
                const uint32_t a0 = sAu[r0];
                const uint32_t a1 = sAu[r0 + 8 * SRS];
                const uint32_t a2 = sAu[r0 + 4];
                const uint32_t a3 = sAu[r0 + 8 * SRS + 4];
#pragma unroll
                for (int n = 0; n < 8; ++n) {
                    const float2 bb = __ldg(bp + (ks * 8 + n) * 32);
                    mma_tf32(acc[n], a0, a1, a2, a3,
                             __float_as_uint(bb.x), __float_as_uint(bb.y));
                }
            }
        }
    }

    // q tile -> smem (fp32). c0,c1 -> row rbase; c2,c3 -> row rbase+8.
    if (w < 8) {
#pragma unroll
        for (int n = 0; n < 8; ++n) {
            const int col = 8 * n + 2 * tig;
            *reinterpret_cast<float2*>(q_sm + rbase * QST + col)       = make_float2(acc[n][0], acc[n][1]);
            *reinterpret_cast<float2*>(q_sm + (rbase + 8) * QST + col) = make_float2(acc[n][2], acc[n][3]);
        }
    }
    __syncthreads();

    // ======================= Phase 2: weights =======================
    // 16 warps scan 8 l-rows each; lane holds cols 2lane, 2lane+1.
    {
        const int r0 = 8 * w;
        float2 p = make_float2(0.f, 0.f);
        if (w > 0) p = *reinterpret_cast<const float2*>(q_sm + (r0 - 1) * QST + 2 * lane);
        for (int r = r0; r < r0 + 8; ++r) {
            float2 v = *reinterpret_cast<const float2*>(q_sm + r * QST + 2 * lane);
            float nn = v.x * v.x + v.y * v.y;
            float cc = v.x * p.x + v.y * p.y;
#pragma unroll
            for (int off = 16; off; off >>= 1) {
                nn += __shfl_xor_sync(0xffffffffu, nn, off);
                cc += __shfl_xor_sync(0xffffffffu, cc, off);
            }
            if (lane == 0) {
                nrm[r] = fmaxf(nn, 1e-5f);
                if (r > 0) crs[r - 1] = cc;
            }
            p = v;
        }
    }
    __syncthreads();

    if (tid < LDIM) {
        const int l  = tid;
        const int sz = size[b];
        float a0 = -1e30f, a2 = -1e30f;
        if (l >= 1 && l < sz)
            a0 = crs[l - 1] / (nrm[l - 1] * nrm[l]);
        int lim2 = sz - 1; if (lim2 < 0) lim2 = 0;
        if (l < lim2)
            a2 = crs[l] / (nrm[l] * nrm[l + 1]);

        float mx = fmaxf(1.0f, fmaxf(a0, a2));
        float e0 = expf(a0 - mx);
        float e1 = expf(1.0f - mx);
        float e2 = expf(a2 - mx);
        float inv = 1.0f / (e0 + e1 + e2);
        wsm[l] = make_float2(e0 * inv, e2 * inv);
    }
    __syncthreads();

    // ======================= Phase 3: combine (smem-resident S) ==============
    float4* o4 = reinterpret_cast<float4*>(out);
    for (int idx = tid; idx < LDIM * 75; idx += NTHR) {
        const int l = idx / 75;
        const int j = idx - l * 75;

        const float2 ww = wsm[l];
        const float w0 = ww.x, w2 = ww.y, w1 = 1.0f - w0 - w2;

        const float4 cu = *reinterpret_cast<const float4*>(s_sm + l * SRS + 4 * j);
        float4 r;
        r.x = w1 * cu.x; r.y = w1 * cu.y; r.z = w1 * cu.z; r.w = w1 * cu.w;
        if (l > 0) {
            const float4 pv = *reinterpret_cast<const float4*>(s_sm + (l - 1) * SRS + 4 * j);
            r.x = fmaf(w0, pv.x, r.x); r.y = fmaf(w0, pv.y, r.y);
            r.z = fmaf(w0, pv.z, r.z); r.w = fmaf(w0, pv.w, r.w);
        }
        if (l < LDIM - 1) {
            const float4 nx = *reinterpret_cast<const float4*>(s_sm + (l + 1) * SRS + 4 * j);
            r.x = fmaf(w2, nx.x, r.x); r.y = fmaf(w2, nx.y, r.y);
            r.z = fmaf(w2, nx.z, r.z); r.w = fmaf(w2, nx.w, r.w);
        }
        __stcs(o4 + ((size_t)l * BDIM + b) * 75 + j, r);
    }
}

// ---------------------------------------------------------------------------
extern "C" void kernel_launch(void* const* d_in, const int* in_sizes, int n_in,
                              void* d_out, int out_size) {
    const float* sentence = nullptr;
    const int*   size_arr = nullptr;
    const float* proj     = nullptr;
    for (int i = 0; i < n_in; ++i) {
        if (in_sizes[i] == LDIM * BDIM * DDIM)      sentence = (const float*)d_in[i];
        else if (in_sizes[i] == DDIM * HDIM)        proj     = (const float*)d_in[i];
        else if (in_sizes[i] == BDIM)               size_arr = (const int*)d_in[i];
    }
    float* out = (float*)d_out;

    const int smem_bytes = LDIM * SRS * 4      // S column   157696
                         + LDIM * QST * 4      // q tile      33792
                         + 2 * LDIM * 4        // nrm, crs     1024
                         + LDIM * 8;           // weights      1024
    cudaFuncSetAttribute(k_fused, cudaFuncAttributeMaxDynamicSharedMemorySize,
                         smem_bytes);

    k_packB<<<(NCH * 1024 + 255) / 256, 256>>>(proj);
    k_fused<<<BDIM, NTHR, smem_bytes>>>(sentence, size_arr, out);
}

// round 9
// speedup vs baseline: 1.1882x; 1.1243x over previous
#include <cuda_runtime.h>
#include <cstdint>

// Problem dims
#define LDIM 128
#define BDIM 2048
#define DDIM 300
#define HDIM 60

// Fused-kernel layout: one CTA = one b, one 30-row l-segment
#define KC    32
#define NCH   10
#define SRS   308          // S smem row stride (floats); (g*20+tig)%32 all distinct
#define QST   66           // q smem row stride (floats)
#define NTHR  256
#define ROWS  32           // smem rows: global l0-1 .. l0+30  (2 full m16 tiles)
#define OUTR  30           // outputs per segment
#define NSEG  5            // ceil(128/30)

// Pre-packed B fragments (tf32 bits), 80 KB, L2-resident
__device__ float2 g_bpack[NCH * 1024];

__device__ __forceinline__ uint32_t smem_u32(const void* p) {
    uint32_t a;
    asm("{ .reg .u64 t; cvta.to.shared.u64 t, %1; cvt.u32.u64 %0, t; }" : "=r"(a) : "l"(p));
    return a;
}
__device__ __forceinline__ uint32_t f2tf32(float x) {
    uint32_t u;
    asm("cvt.rna.tf32.f32 %0, %1;" : "=r"(u) : "f"(x));
    return u;
}
__device__ __forceinline__ void mma_tf32(float* c, uint32_t a0, uint32_t a1,
                                         uint32_t a2, uint32_t a3,
                                         uint32_t b0, uint32_t b1) {
    asm volatile(
        "mma.sync.aligned.m16n8k8.row.col.f32.tf32.tf32.f32 "
        "{%0,%1,%2,%3}, {%4,%5,%6,%7}, {%8,%9}, {%0,%1,%2,%3};"
        : "+f"(c[0]), "+f"(c[1]), "+f"(c[2]), "+f"(c[3])
        : "r"(a0), "r"(a1), "r"(a2), "r"(a3), "r"(b0), "r"(b1));
}
__device__ __forceinline__ void cp16(uint32_t dst, const void* src, int sz) {
    asm volatile("cp.async.cg.shared.global [%0], [%1], 16, %2;"
                 :: "r"(dst), "l"(src), "r"(sz));
}
#define CP_COMMIT() asm volatile("cp.async.commit_group;" ::: "memory")

__device__ __forceinline__ void cp_wait_n(int n) {
    switch (n) {
        case 0: asm volatile("cp.async.wait_group 0;" ::: "memory"); break;
        case 1: asm volatile("cp.async.wait_group 1;" ::: "memory"); break;
        case 2: asm volatile("cp.async.wait_group 2;" ::: "memory"); break;
        case 3: asm volatile("cp.async.wait_group 3;" ::: "memory"); break;
        case 4: asm volatile("cp.async.wait_group 4;" ::: "memory"); break;
        case 5: asm volatile("cp.async.wait_group 5;" ::: "memory"); break;
        case 6: asm volatile("cp.async.wait_group 6;" ::: "memory"); break;
        case 7: asm volatile("cp.async.wait_group 7;" ::: "memory"); break;
        case 8: asm volatile("cp.async.wait_group 8;" ::: "memory"); break;
        default: asm volatile("cp.async.wait_group 9;" ::: "memory"); break;
    }
}

// ---------------------------------------------------------------------------
// Kernel 0 (one-shot, tiny): pack B fragments for all chunks (zero-padded
// past K=300 and H=60).
// ---------------------------------------------------------------------------
__global__ void k_packB(const float* __restrict__ P) {
    const int e = blockIdx.x * 256 + threadIdx.x;   // < 10240
    if (e >= NCH * 1024) return;
    const int c  = e >> 10;
    const int r  = e & 1023;
    const int ks = r >> 8;
    const int n  = (r >> 5) & 7;
    const int ln = r & 31;
    const int tg = ln & 3, g = ln >> 2;
    const int k  = c * KC + 8 * ks + tg;
    const int h  = 8 * n + g;
    float b0 = (k < DDIM && h < HDIM)     ? P[(size_t)k * HDIM + h]       : 0.f;
    float b1 = (k + 4 < DDIM && h < HDIM) ? P[(size_t)(k + 4) * HDIM + h] : 0.f;
    float2 v;
    v.x = __uint_as_float(f2tf32(b0));
    v.y = __uint_as_float(f2tf32(b1));
    g_bpack[e] = v;
}

// ---------------------------------------------------------------------------
// Fused kernel: blockIdx -> (b = blk/NSEG, seg = blk%NSEG), l0 = 30*seg.
// Smem holds S global rows l0-1..l0+30 (32 rows x 308) + q (32 x 66).
//  1) all cp.async chunks upfront; per-chunk wait + MMA (warps 0-3)
//  2) norms / neighbor-dots / masked softmax for l in [l0, l0+30)
//  3) combine from smem, streaming stores to out
// Local row i <-> global row l0-1+i. Garbage rows (global <0 or >127) feed
// only masked/guarded terms and are never multiplied in.
// Smem total ~48.4 KB -> 4 CTAs/SM.
// ---------------------------------------------------------------------------
__global__ __launch_bounds__(NTHR, 4) void k_fused(const float* __restrict__ S,
                                                   const int* __restrict__ size,
                                                   float* __restrict__ out) {
    extern __shared__ float sm[];
    float*  s_sm = sm;                        // [ROWS][SRS]
    float*  q_sm = sm + ROWS * SRS;           // [ROWS][QST]
    float*  nrm  = q_sm + ROWS * QST;         // [ROWS]
    float*  crs  = nrm + ROWS;                // [ROWS]
    float2* wsm  = reinterpret_cast<float2*>(crs + ROWS);  // [OUTR]
    const uint32_t* sAu = reinterpret_cast<const uint32_t*>(s_sm);

    const int tid  = threadIdx.x;
    const int w    = tid >> 5;
    const int lane = tid & 31;
    const int g    = lane >> 2;
    const int tig  = lane & 3;
    const int blk  = blockIdx.x;
    const int b    = blk / NSEG;
    const int l0   = (blk - b * NSEG) * OUTR;

    const uint32_t s_u = smem_u32(s_sm);

    // ---- issue ALL chunks: exactly 1 cp16 per thread per chunk ----
    // thread -> (row = tid>>3, kq = (tid&7)*4); global row = l0-1+row
    {
        const int row  = tid >> 3;
        const int kq   = (tid & 7) * 4;
        const int grow = l0 - 1 + row;
        const bool gv  = (grow >= 0 && grow <= LDIM - 1);
        const float* base = gv ? S + ((size_t)grow * BDIM + b) * DDIM + kq : S;
        const uint32_t dst0 = s_u + ((row * SRS + kq) << 2);
#pragma unroll
        for (int c = 0; c < NCH; ++c) {
            const int k = c * KC + kq;
            if (gv && k < SRS) {
                const int sz = (k + 4 <= DDIM) ? 16 : 0;   // 300..307 zero-fill
                cp16(dst0 + (c * KC << 2), sz ? (base + c * KC) : S, sz);
            }
            CP_COMMIT();
        }
    }

    // ---- MMA: warps 0-3; warp = (tile t = w>>1, n-half nh = w&1) ----
    float acc[4][4];
#pragma unroll
    for (int n = 0; n < 4; ++n)
#pragma unroll
        for (int i = 0; i < 4; ++i) acc[n][i] = 0.f;

    const int t     = w >> 1;
    const int nh    = w & 1;
    const int rbase = 16 * t + g;

#pragma unroll
    for (int c = 0; c < NCH; ++c) {
        cp_wait_n(NCH - 1 - c);
        __syncthreads();

        if (w < 4) {
            const float2* bp = g_bpack + c * 1024 + lane;
            const int nks = (c == NCH - 1) ? 2 : 4;   // chunk 9: k>=304 not in smem
#pragma unroll
            for (int ks = 0; ks < 4; ++ks) {
                if (ks >= nks) break;
                const int r0 = rbase * SRS + c * KC + 8 * ks + tig;
                const uint32_t a0 = sAu[r0];
                const uint32_t a1 = sAu[r0 + 8 * SRS];
                const uint32_t a2 = sAu[r0 + 4];
                const uint32_t a3 = sAu[r0 + 8 * SRS + 4];
#pragma unroll
                for (int n = 0; n < 4; ++n) {
                    const float2 bb = __ldg(bp + (ks * 8 + 4 * nh + n) * 32);
                    mma_tf32(acc[n], a0, a1, a2, a3,
                             __float_as_uint(bb.x), __float_as_uint(bb.y));
                }
            }
        }
    }

    // q tile -> smem. c0,c1 -> row rbase; c2,c3 -> row rbase+8.
    if (w < 4) {
#pragma unroll
        for (int n = 0; n < 4; ++n) {
            const int col = 8 * (4 * nh + n) + 2 * tig;
            *reinterpret_cast<float2*>(q_sm + rbase * QST + col)       = make_float2(acc[n][0], acc[n][1]);
            *reinterpret_cast<float2*>(q_sm + (rbase + 8) * QST + col) = make_float2(acc[n][2], acc[n][3]);
        }
    }
    __syncthreads();

    // ======================= Phase 2: weights =======================
    // 8 warps scan 4 local q-rows each; lane holds cols 2lane, 2lane+1.
    {
        const int r0 = 4 * w;
        float2 p = make_float2(0.f, 0.f);
        if (w > 0) p = *reinterpret_cast<const float2*>(q_sm + (r0 - 1) * QST + 2 * lane);
        for (int r = r0; r < r0 + 4; ++r) {
            float2 v = *reinterpret_cast<const float2*>(q_sm + r * QST + 2 * lane);
            float nn = v.x * v.x + v.y * v.y;
            float cc = v.x * p.x + v.y * p.y;
#pragma unroll
            for (int off = 16; off; off >>= 1) {
                nn += __shfl_xor_sync(0xffffffffu, nn, off);
                cc += __shfl_xor_sync(0xffffffffu, cc, off);
            }
            if (lane == 0) {
                nrm[r] = fmaxf(nn, 1e-5f);
                if (r > 0) crs[r - 1] = cc;
            }
            p = v;
        }
    }
    __syncthreads();

    if (tid < OUTR) {
        const int l = l0 + tid;
        if (l < LDIM) {
            const int sz = __ldg(size + b);
            const int i  = l - l0;            // local: nrm/crs index of global l-1
            float a0 = -1e30f, a2 = -1e30f;
            if (l >= 1 && l < sz)
                a0 = crs[i] / (nrm[i] * nrm[i + 1]);
            int lim2 = sz - 1; if (lim2 < 0) lim2 = 0;
            if (l < lim2)
                a2 = crs[i + 1] / (nrm[i + 1] * nrm[i + 2]);

            float mx = fmaxf(1.0f, fmaxf(a0, a2));
            float e0 = expf(a0 - mx);
            float e1 = expf(1.0f - mx);
            float e2 = expf(a2 - mx);
            float inv = 1.0f / (e0 + e1 + e2);
            wsm[tid] = make_float2(e0 * inv, e2 * inv);
        }
    }
    __syncthreads();

    // ======================= Phase 3: combine (smem-resident S) ==============
    float4* o4 = reinterpret_cast<float4*>(out);
    for (int idx = tid; idx < OUTR * 75; idx += NTHR) {
        const int lrel = idx / 75;
        const int l    = l0 + lrel;
        if (l >= LDIM) break;
        const int j = idx - lrel * 75;

        const float2 ww = wsm[lrel];
        const float w0 = ww.x, w2 = ww.y, w1 = 1.0f - w0 - w2;

        const float4 cu = *reinterpret_cast<const float4*>(s_sm + (lrel + 1) * SRS + 4 * j);
        float4 r;
        r.x = w1 * cu.x; r.y = w1 * cu.y; r.z = w1 * cu.z; r.w = w1 * cu.w;
        if (l > 0) {
            const float4 pv = *reinterpret_cast<const float4*>(s_sm + lrel * SRS + 4 * j);
            r.x = fmaf(w0, pv.x, r.x); r.y = fmaf(w0, pv.y, r.y);
            r.z = fmaf(w0, pv.z, r.z); r.w = fmaf(w0, pv.w, r.w);
        }
        if (l < LDIM - 1) {
            const float4 nx = *reinterpret_cast<const float4*>(s_sm + (lrel + 2) * SRS + 4 * j);
            r.x = fmaf(w2, nx.x, r.x); r.y = fmaf(w2, nx.y, r.y);
            r.z = fmaf(w2, nx.z, r.z); r.w = fmaf(w2, nx.w, r.w);
        }
        __stcs(o4 + ((size_t)l * BDIM + b) * 75 + j, r);
    }
}

// ---------------------------------------------------------------------------
extern "C" void kernel_launch(void* const* d_in, const int* in_sizes, int n_in,
                              void* d_out, int out_size) {
    const float* sentence = nullptr;
    const int*   size_arr = nullptr;
    const float* proj     = nullptr;
    for (int i = 0; i < n_in; ++i) {
        if (in_sizes[i] == LDIM * BDIM * DDIM)      sentence = (const float*)d_in[i];
        else if (in_sizes[i] == DDIM * HDIM)        proj     = (const float*)d_in[i];
        else if (in_sizes[i] == BDIM)               size_arr = (const int*)d_in[i];
    }
    float* out = (float*)d_out;

    const int smem_bytes = ROWS * SRS * 4      // S rows      39424
                         + ROWS * QST * 4      // q tile       8448
                         + 2 * ROWS * 4        // nrm, crs      256
                         + OUTR * 8;           // weights       240
    cudaFuncSetAttribute(k_fused, cudaFuncAttributeMaxDynamicSharedMemorySize,
                         smem_bytes);

    k_packB<<<(NCH * 1024 + 255) / 256, 256>>>(proj);
    k_fused<<<BDIM * NSEG, NTHR, smem_bytes>>>(sentence, size_arr, out);
}

// round 10
// speedup vs baseline: 1.7141x; 1.4426x over previous
#include <cuda_runtime.h>
#include <cuda_fp16.h>
#include <cstdint>

// Problem dims
#define LDIM 128
#define BDIM 2048
#define DDIM 300
#define HDIM 60

// Fused-kernel layout: one CTA = one b, one 30-row l-segment
#define KC     32
#define NCH    10
#define SRS2   312         // S smem row stride (halfs); (g*156+tig)%32 distinct
#define QST    66          // q smem row stride (floats)
#define NTHR   256
#define ROWS   32          // smem rows: global l0-1 .. l0+30 (2 m16 tiles)
#define OUTR   30
#define NSEG   5
#define KSTEPS 19          // ceil(300/16): k 0..303, zero-padded

// Pre-packed B fragments (fp16 pairs), 38.9 KB, L2-resident
__device__ uint2 g_bpackh[KSTEPS * 256];

__device__ __forceinline__ void mma_f16(float* c, uint32_t a0, uint32_t a1,
                                        uint32_t a2, uint32_t a3,
                                        uint32_t b0, uint32_t b1) {
    asm volatile(
        "mma.sync.aligned.m16n8k16.row.col.f32.f16.f16.f32 "
        "{%0,%1,%2,%3}, {%4,%5,%6,%7}, {%8,%9}, {%0,%1,%2,%3};"
        : "+f"(c[0]), "+f"(c[1]), "+f"(c[2]), "+f"(c[3])
        : "r"(a0), "r"(a1), "r"(a2), "r"(a3), "r"(b0), "r"(b1));
}
__device__ __forceinline__ float4 lds_h4(const __half* p) {
    uint2 u = *reinterpret_cast<const uint2*>(p);
    __half2 a = *reinterpret_cast<__half2*>(&u.x);
    __half2 b = *reinterpret_cast<__half2*>(&u.y);
    float2 fa = __half22float2(a), fb = __half22float2(b);
    return make_float4(fa.x, fa.y, fb.x, fb.y);
}

// ---------------------------------------------------------------------------
// Kernel 0 (one-shot, tiny): pack B fragments, fp16.
// Entry (ks, n, lane): b0 = (P[k][h], P[k+1][h]), b1 = (P[k+8][h], P[k+9][h])
// with k = 16*ks + 2*tig, h = 8*n + g; zero outside K=300 / H=60.
// ---------------------------------------------------------------------------
__global__ void k_packB(const float* __restrict__ P) {
    const int e = blockIdx.x * 256 + threadIdx.x;
    if (e >= KSTEPS * 256) return;
    const int ks = e >> 8;
    const int n  = (e >> 5) & 7;
    const int ln = e & 31;
    const int tg = ln & 3, g = ln >> 2;
    const int k  = ks * 16 + 2 * tg;
    const int h  = 8 * n + g;
    float v[4] = {0.f, 0.f, 0.f, 0.f};
    if (h < HDIM) {
        if (k     < DDIM) v[0] = P[(size_t)(k)     * HDIM + h];
        if (k + 1 < DDIM) v[1] = P[(size_t)(k + 1) * HDIM + h];
        if (k + 8 < DDIM) v[2] = P[(size_t)(k + 8) * HDIM + h];
        if (k + 9 < DDIM) v[3] = P[(size_t)(k + 9) * HDIM + h];
    }
    __half2 b0 = __floats2half2_rn(v[0], v[1]);
    __half2 b1 = __floats2half2_rn(v[2], v[3]);
    uint2 u;
    u.x = *reinterpret_cast<uint32_t*>(&b0);
    u.y = *reinterpret_cast<uint32_t*>(&b1);
    g_bpackh[e] = u;
}

// ---------------------------------------------------------------------------
// Fused kernel: blockIdx -> (b = blk/NSEG, seg), l0 = 30*seg.
// Smem: S rows l0-1..l0+30 as fp16 [32][312] | q fp32 [32][66] | aux.
//  1) stage: LDG.128 -> cvt fp16 -> STS.64 (all chunks), one barrier
//  2) MMA m16n8k16 fp16 over all 8 warps (warp = tile x n-quarter)
//  3) norms / neighbor-dots / masked softmax
//  4) combine from fp16 smem, streaming float4 stores
// Smem 28.9 KB -> 5 CTAs/SM.
// ---------------------------------------------------------------------------
__global__ __launch_bounds__(NTHR, 5) void k_fused(const float* __restrict__ S,
                                                   const int* __restrict__ size,
                                                   float* __restrict__ out) {
    extern __shared__ char smraw[];
    __half* s_h  = reinterpret_cast<__half*>(smraw);             // [ROWS][SRS2]
    float*  q_sm = reinterpret_cast<float*>(smraw + ROWS * SRS2 * 2);  // [ROWS][QST]
    float*  nrm  = q_sm + ROWS * QST;                            // [ROWS]
    float*  crs  = nrm + ROWS;                                   // [ROWS]
    float2* wsm  = reinterpret_cast<float2*>(crs + ROWS);        // [OUTR]
    const uint32_t* sh32 = reinterpret_cast<const uint32_t*>(s_h);

    const int tid  = threadIdx.x;
    const int w    = tid >> 5;
    const int lane = tid & 31;
    const int g    = lane >> 2;
    const int tig  = lane & 3;
    const int blk  = blockIdx.x;
    const int b    = blk / NSEG;
    const int l0   = (blk - b * NSEG) * OUTR;

    // ---- stage all S rows: thread = (row = tid>>3, kq4 = tid&7) ----
    {
        const int row  = tid >> 3;
        const int kq4  = tid & 7;
        const int grow = l0 - 1 + row;
        const bool gv  = (grow >= 0 && grow < LDIM);
        const float* base = S + ((size_t)(gv ? grow : 0) * BDIM + b) * DDIM;
        __half* drow = s_h + row * SRS2;
#pragma unroll
        for (int c = 0; c < NCH; ++c) {
            const int k0 = c * KC + kq4 * 4;
            if (k0 >= SRS2) break;
            float4 v = make_float4(0.f, 0.f, 0.f, 0.f);
            if (gv && k0 + 4 <= DDIM) v = *reinterpret_cast<const float4*>(base + k0);
            __half2 h01 = __floats2half2_rn(v.x, v.y);
            __half2 h23 = __floats2half2_rn(v.z, v.w);
            uint2 u;
            u.x = *reinterpret_cast<uint32_t*>(&h01);
            u.y = *reinterpret_cast<uint32_t*>(&h23);
            *reinterpret_cast<uint2*>(drow + k0) = u;
        }
    }
    __syncthreads();

    // ---- MMA: all 8 warps; warp = (tile t = w>>2, n-quarter nq = w&3) ----
    float acc[2][4];
#pragma unroll
    for (int n = 0; n < 2; ++n)
#pragma unroll
        for (int i = 0; i < 4; ++i) acc[n][i] = 0.f;

    const int t     = w >> 2;
    const int nq    = w & 3;
    const int rbase = 16 * t + g;

#pragma unroll
    for (int ks = 0; ks < KSTEPS; ++ks) {
        // u32-index view: row stride SRS2/2 = 156, k-pair index = 8*ks + tig
        const int base0 = rbase * 156 + ks * 8 + tig;
        const uint32_t a0 = sh32[base0];
        const uint32_t a1 = sh32[base0 + 8 * 156];
        const uint32_t a2 = sh32[base0 + 4];
        const uint32_t a3 = sh32[base0 + 8 * 156 + 4];
#pragma unroll
        for (int nn = 0; nn < 2; ++nn) {
            const uint2 bb = __ldg(&g_bpackh[(ks * 8 + 2 * nq + nn) * 32 + lane]);
            mma_f16(acc[nn], a0, a1, a2, a3, bb.x, bb.y);
        }
    }

    // q tile -> smem. c0,c1 -> row rbase; c2,c3 -> row rbase+8.
#pragma unroll
    for (int nn = 0; nn < 2; ++nn) {
        const int col = 8 * (2 * nq + nn) + 2 * tig;
        *reinterpret_cast<float2*>(q_sm + rbase * QST + col)       = make_float2(acc[nn][0], acc[nn][1]);
        *reinterpret_cast<float2*>(q_sm + (rbase + 8) * QST + col) = make_float2(acc[nn][2], acc[nn][3]);
    }
    __syncthreads();

    // ---- weights: 8 warps scan 4 local q-rows each; lane = col pair ----
    {
        const int r0 = 4 * w;
        float2 p = make_float2(0.f, 0.f);
        if (w > 0) p = *reinterpret_cast<const float2*>(q_sm + (r0 - 1) * QST + 2 * lane);
        for (int r = r0; r < r0 + 4; ++r) {
            float2 v = *reinterpret_cast<const float2*>(q_sm + r * QST + 2 * lane);
            float nn = v.x * v.x + v.y * v.y;
            float cc = v.x * p.x + v.y * p.y;
#pragma unroll
            for (int off = 16; off; off >>= 1) {
                nn += __shfl_xor_sync(0xffffffffu, nn, off);
                cc += __shfl_xor_sync(0xffffffffu, cc, off);
            }
            if (lane == 0) {
                nrm[r] = fmaxf(nn, 1e-5f);
                if (r > 0) crs[r - 1] = cc;
            }
            p = v;
        }
    }
    __syncthreads();

    if (tid < OUTR) {
        const int l = l0 + tid;
        if (l < LDIM) {
            const int sz = __ldg(size + b);
            const int i  = tid;               // nrm/crs index of global row l-1
            float a0 = -1e30f, a2 = -1e30f;
            if (l >= 1 && l < sz)
                a0 = crs[i] / (nrm[i] * nrm[i + 1]);
            int lim2 = sz - 1; if (lim2 < 0) lim2 = 0;
            if (l < lim2)
                a2 = crs[i + 1] / (nrm[i + 1] * nrm[i + 2]);

            float mx = fmaxf(1.0f, fmaxf(a0, a2));
            float e0 = expf(a0 - mx);
            float e1 = expf(1.0f - mx);
            float e2 = expf(a2 - mx);
            float inv = 1.0f / (e0 + e1 + e2);
            wsm[tid] = make_float2(e0 * inv, e2 * inv);
        }
    }
    __syncthreads();

    // ---- combine from fp16 smem; streaming float4 stores ----
    float4* o4 = reinterpret_cast<float4*>(out);
    for (int idx = tid; idx < OUTR * 75; idx += NTHR) {
        const int lrel = idx / 75;
        const int l    = l0 + lrel;
        if (l >= LDIM) break;
        const int j = idx - lrel * 75;

        const float2 ww = wsm[lrel];
        const float w0 = ww.x, w2 = ww.y, w1 = 1.0f - w0 - w2;

        const float4 cu = lds_h4(s_h + (lrel + 1) * SRS2 + 4 * j);
        float4 r;
        r.x = w1 * cu.x; r.y = w1 * cu.y; r.z = w1 * cu.z; r.w = w1 * cu.w;
        if (l > 0) {
            const float4 pv = lds_h4(s_h + lrel * SRS2 + 4 * j);
            r.x = fmaf(w0, pv.x, r.x); r.y = fmaf(w0, pv.y, r.y);
            r.z = fmaf(w0, pv.z, r.z); r.w = fmaf(w0, pv.w, r.w);
        }
        if (l < LDIM - 1) {
            const float4 nx = lds_h4(s_h + (lrel + 2) * SRS2 + 4 * j);
            r.x = fmaf(w2, nx.x, r.x); r.y = fmaf(w2, nx.y, r.y);
            r.z = fmaf(w2, nx.z, r.z); r.w = fmaf(w2, nx.w, r.w);
        }
        __stcs(o4 + ((size_t)l * BDIM + b) * 75 + j, r);
    }
}

// ---------------------------------------------------------------------------
extern "C" void kernel_launch(void* const* d_in, const int* in_sizes, int n_in,
                              void* d_out, int out_size) {
    const float* sentence = nullptr;
    const int*   size_arr = nullptr;
    const float* proj     = nullptr;
    for (int i = 0; i < n_in; ++i) {
        if (in_sizes[i] == LDIM * BDIM * DDIM)      sentence = (const float*)d_in[i];
        else if (in_sizes[i] == DDIM * HDIM)        proj     = (const float*)d_in[i];
        else if (in_sizes[i] == BDIM)               size_arr = (const int*)d_in[i];
    }
    float* out = (float*)d_out;

    const int smem_bytes = ROWS * SRS2 * 2     // S fp16     19968
                         + ROWS * QST * 4      // q tile      8448
                         + 2 * ROWS * 4        // nrm, crs     256
                         + OUTR * 8;           // weights      240
    cudaFuncSetAttribute(k_fused, cudaFuncAttributeMaxDynamicSharedMemorySize,
                         smem_bytes);

    k_packB<<<(KSTEPS * 256 + 255) / 256, 256>>>(proj);
    k_fused<<<BDIM * NSEG, NTHR, smem_bytes>>>(sentence, size_arr, out);
}